// round 2
// baseline (speedup 1.0000x reference)
#include <cuda_runtime.h>
#include <math.h>

// Scratch accumulators: per batch {stc_sum, str_sum, pos_count}
#define MAXB 16
__device__ float g_acc[3 * MAXB];

__global__ void zero_acc_kernel() {
    int i = threadIdx.x;
    if (i < 3 * MAXB) g_acc[i] = 0.0f;
}

#define MAXK 128

__global__ void ainno_loss_kernel(const float* __restrict__ ss,
                                  const float* __restrict__ anchors,
                                  const float* __restrict__ gt,
                                  int A, int K) {
    const int b = blockIdx.y;
    const int tid = threadIdx.x;

    __shared__ float gx1[MAXK], gy1[MAXK], gx2[MAXK], gy2[MAXK], ga[MAXK];
    __shared__ float s_acc[3];

    if (tid < 3) s_acc[tid] = 0.0f;
    for (int k = tid; k < K; k += blockDim.x) {
        float4 g = *(const float4*)(gt + ((size_t)b * K + k) * 4);
        gx1[k] = g.x;
        gy1[k] = g.y;
        gx2[k] = g.x + g.z;
        gy2[k] = g.y + g.w;
        ga[k]  = g.z * g.w;
    }
    __syncthreads();

    const int a = blockIdx.x * blockDim.x + tid;

    float stc = 0.0f, strl = 0.0f, pc = 0.0f;

    if (a < A) {
        float4 an = *(const float4*)(anchors + (size_t)a * 4);
        const float ax1 = an.x, ay1 = an.y;
        const float ax2 = an.x + an.z, ay2 = an.y + an.w;
        const float aarea = an.z * an.w;

        float best = -1.0f;
        int bidx = 0;
#pragma unroll 8
        for (int k = 0; k < K; k++) {
            float lx = fmaxf(ax1, gx1[k]);
            float ly = fmaxf(ay1, gy1[k]);
            float rx = fminf(ax2, gx2[k]);
            float ry = fminf(ay2, gy2[k]);
            float w = fmaxf(rx - lx, 0.0f);
            float h = fmaxf(ry - ly, 0.0f);
            float inter = w * h;
            float iou = __fdividef(inter, aarea + ga[k] - inter);
            bool better = iou > best;          // first-max wins (matches jnp.argmax)
            best = better ? iou : best;
            bidx = better ? k : bidx;
        }

        const float* row = ss + ((size_t)b * A + a) * 6;
        const float x = row[4];                 // logits
        const bool pos = best >= 0.5f;
        const bool neg = best < 0.4f;

        if (pos) {
            // focal, t=1: 0.25 * (-log p) * (1-p)^2
            float emx = expf(-x);
            float p = 1.0f / (1.0f + emx);
            float omp = 1.0f - p;
            stc = 0.25f * log1pf(emx) * omp * omp;

            pc = 1.0f;
            // elementwise IoU(pred box, matched gt box)
            float px = row[0], py = row[1], pw = row[2], ph = row[3];
            float px2 = px + pw, py2 = py + ph;
            float pa = pw * ph;
            float lx = fmaxf(px,  gx1[bidx]);
            float ly = fmaxf(py,  gy1[bidx]);
            float rx = fminf(px2, gx2[bidx]);
            float ry = fminf(py2, gy2[bidx]);
            float w = fmaxf(rx - lx, 0.0f);
            float h = fmaxf(ry - ly, 0.0f);
            float ei = w * h;
            float eiou = ei / (pa + ga[bidx] - ei);
            strl = -logf(eiou + 0.01f);
        } else if (neg) {
            // focal, t=0: 0.75 * (-log(1-p)) * p^2
            float emx = expf(-x);
            float p = 1.0f / (1.0f + emx);
            stc = 0.75f * log1pf(expf(x)) * p * p;
        }
    }

    // warp-level tree reduction of (stc, strl, pc)
#pragma unroll
    for (int off = 16; off; off >>= 1) {
        stc  += __shfl_xor_sync(0xffffffffu, stc,  off);
        strl += __shfl_xor_sync(0xffffffffu, strl, off);
        pc   += __shfl_xor_sync(0xffffffffu, pc,   off);
    }
    if ((tid & 31) == 0) {
        atomicAdd(&s_acc[0], stc);
        atomicAdd(&s_acc[1], strl);
        atomicAdd(&s_acc[2], pc);
    }
    __syncthreads();
    if (tid == 0) {
        atomicAdd(&g_acc[b * 3 + 0], s_acc[0]);
        atomicAdd(&g_acc[b * 3 + 1], s_acc[1]);
        atomicAdd(&g_acc[b * 3 + 2], s_acc[2]);
    }
}

__global__ void finalize_kernel(float* __restrict__ out, int B) {
    float tot = 0.0f;
    for (int b = 0; b < B; b++) {
        float pcv = g_acc[b * 3 + 2];
        float safe = (pcv > 0.0f) ? pcv : 1.0f;
        tot += g_acc[b * 3 + 0] / safe;
        tot += (pcv > 0.0f) ? (g_acc[b * 3 + 1] / pcv) : 0.0f;
    }
    out[0] = tot / (float)B;
}

extern "C" void kernel_launch(void* const* d_in, const int* in_sizes, int n_in,
                              void* d_out, int out_size) {
    const float* ss      = (const float*)d_in[0];  // (B, A, 6)
    const float* anchors = (const float*)d_in[1];  // (A, 4)
    const float* gt      = (const float*)d_in[2];  // (B, K, 4)

    const int A = in_sizes[1] / 4;
    const int B = in_sizes[0] / (6 * A);
    const int K = in_sizes[2] / (4 * B);

    float* out = (float*)d_out;

    zero_acc_kernel<<<1, 64>>>();

    const int threads = 256;
    dim3 grid((A + threads - 1) / threads, B);
    ainno_loss_kernel<<<grid, threads>>>(ss, anchors, gt, A, K);

    finalize_kernel<<<1, 1>>>(out, B);
}